// round 14
// baseline (speedup 1.0000x reference)
#include <cuda_runtime.h>
#include <cuda_fp16.h>
#include <math.h>
#include <stdint.h>

#define BB     4
#define SEQ    2048
#define DIMD   1024
#define HEADS  16
#define DH     64
#define ROT    32
#define BH     (BB*HEADS)          // 64
#define MROWS  (BB*SEQ)            // 8192
#define OUT_ELEMS ((size_t)MROWS*DIMD)

// ---------------- scratch (fp16) ----------------
__device__ __half g_Q[(size_t)BH*SEQ*DH];
__device__ __half g_K[(size_t)BH*SEQ*DH];
__device__ __half g_V[(size_t)BH*SEQ*DH];
__device__ __half g_O[(size_t)MROWS*DIMD];
__device__ __half g_X[(size_t)MROWS*DIMD];
__device__ __half g_Wh[(size_t)4*DIMD*DIMD];

// ---------------- helpers ----------------
__device__ __forceinline__ unsigned f2h2(float a, float b) {
    unsigned u;
    asm("cvt.rn.f16x2.f32 %0, %2, %1;" : "=r"(u) : "f"(a), "f"(b));
    return u;
}
__device__ __forceinline__ uint32_t smem_u32(const void* p) {
    uint32_t a;
    asm("{ .reg .u64 t; cvta.to.shared.u64 t, %1; cvt.u32.u64 %0, t; }" : "=r"(a) : "l"(p));
    return a;
}
__device__ __forceinline__ void mma_f16(float d[4], const unsigned a[4],
                                        const unsigned b[2], const float c[4]) {
    asm volatile(
        "mma.sync.aligned.m16n8k16.row.col.f32.f16.f16.f32 "
        "{%0,%1,%2,%3}, {%4,%5,%6,%7}, {%8,%9}, {%10,%11,%12,%13};"
        : "=f"(d[0]), "=f"(d[1]), "=f"(d[2]), "=f"(d[3])
        : "r"(a[0]), "r"(a[1]), "r"(a[2]), "r"(a[3]),
          "r"(b[0]), "r"(b[1]),
          "f"(c[0]), "f"(c[1]), "f"(c[2]), "f"(c[3]));
}
__device__ __forceinline__ void ldsm_x4(unsigned& r0, unsigned& r1,
                                        unsigned& r2, unsigned& r3, uint32_t a) {
    asm volatile("ldmatrix.sync.aligned.m8n8.x4.shared.b16 {%0,%1,%2,%3}, [%4];"
                 : "=r"(r0), "=r"(r1), "=r"(r2), "=r"(r3) : "r"(a));
}
__device__ __forceinline__ void ldsm_x4_t(unsigned& r0, unsigned& r1,
                                          unsigned& r2, unsigned& r3, uint32_t a) {
    asm volatile("ldmatrix.sync.aligned.m8n8.x4.trans.shared.b16 {%0,%1,%2,%3}, [%4];"
                 : "=r"(r0), "=r"(r1), "=r"(r2), "=r"(r3) : "r"(a));
}
#define CPA16(d, s)   asm volatile("cp.async.ca.shared.global [%0], [%1], 16;" :: "r"(d), "l"(s))
#define CPA_COMMIT()  asm volatile("cp.async.commit_group;" ::: "memory")
#define CPA_WAIT(n)   asm volatile("cp.async.wait_group %0;" :: "n"(n) : "memory")
__device__ __forceinline__ void stcs2(float* p, float x, float y) {
    asm volatile("st.global.cs.v2.f32 [%0], {%1,%2};" :: "l"(p), "f"(x), "f"(y));
}

// ---------------- f32 -> f16 conversion (x + 4 weights) ----------------
__global__ void convert_half(const float* __restrict__ x,
                             const float* __restrict__ Wq, const float* __restrict__ Wk,
                             const float* __restrict__ Wv, const float* __restrict__ Wo) {
    size_t i = (size_t)blockIdx.x * blockDim.x + threadIdx.x;
    const size_t XN = OUT_ELEMS / 4;
    const size_t WN = (size_t)DIMD * DIMD / 4;
    const float* src; __half* dst; size_t off;
    if (i < XN)                { src = x;  dst = g_X;               off = i; }
    else if (i < XN + WN)      { src = Wq; dst = g_Wh;              off = i - XN; }
    else if (i < XN + 2 * WN)  { src = Wk; dst = g_Wh + WN * 4;     off = i - XN - WN; }
    else if (i < XN + 3 * WN)  { src = Wv; dst = g_Wh + 2 * WN * 4; off = i - XN - 2 * WN; }
    else                       { src = Wo; dst = g_Wh + 3 * WN * 4; off = i - XN - 3 * WN; }
    float4 v = *(const float4*)(src + off * 4);
    *(uint2*)(dst + off * 4) = make_uint2(f2h2(v.x, v.y), f2h2(v.z, v.w));
}

// ============ pipelined fp16 GEMM (cp.async + ldmatrix) =====================
#define A_STRIDE 80
#define B_STRIDE 272
template <int MODE>
__global__ __launch_bounds__(256) void gemm_pipe(
    const __half* __restrict__ Aglob, const __half* __restrict__ Wbase,
    const float* __restrict__ bo, const float* __restrict__ resid,
    float* __restrict__ Yf)
{
    extern __shared__ char sm[];
    uint32_t sb = smem_u32(sm);
    uint32_t Ab[2] = {sb, sb + 10240};
    uint32_t Bb[2] = {sb + 20480, sb + 20480 + 8704};

    int t = threadIdx.x, lane = t & 31, w = t >> 5;
    int g = lane >> 2, tq = lane & 3;
    int wm = w & 1, wn = w >> 1;
    int row0 = blockIdx.y * 128, col0 = blockIdx.x * 128;

    const __half* Bh;
    __half* Yh = nullptr;
    if (MODE == 0) {
        int z = blockIdx.z;
        Bh = Wbase + (size_t)z * DIMD * DIMD;
        Yh = (z == 0) ? g_Q : (z == 1) ? g_K : g_V;
    } else {
        Bh = Wbase;
    }

    float acc[4][4][4];
#pragma unroll
    for (int i = 0; i < 4; i++)
#pragma unroll
        for (int j = 0; j < 4; j++)
#pragma unroll
            for (int r = 0; r < 4; r++) acc[i][j][r] = 0.f;

    int ar[2], ac[2], br[2], bc[2];
#pragma unroll
    for (int s = 0; s < 2; s++) {
        int idx = t + s * 256;
        ar[s] = idx >> 2;  ac[s] = (idx & 3) * 16;
        br[s] = idx >> 4;  bc[s] = (idx & 15) * 16;
    }

#define ISSUE(p) do { \
    int _buf = (p) & 1; int _k0 = (p) * 32; \
    _Pragma("unroll") \
    for (int s = 0; s < 2; s++) { \
        CPA16(Ab[_buf] + ar[s] * A_STRIDE + ac[s], \
              (const char*)(Aglob + (size_t)(row0 + ar[s]) * DIMD + _k0) + ac[s]); \
        CPA16(Bb[_buf] + br[s] * B_STRIDE + bc[s], \
              (const char*)(Bh + (size_t)(_k0 + br[s]) * DIMD + col0) + bc[s]); \
    } \
} while (0)

    ISSUE(0); CPA_COMMIT();

    for (int p = 0; p < 32; p++) {
        if (p + 1 < 32) { ISSUE(p + 1); CPA_COMMIT(); CPA_WAIT(1); }
        else            { CPA_WAIT(0); }
        __syncthreads();
        int buf = p & 1;
#pragma unroll
        for (int ks = 0; ks < 2; ks++) {
            int kh = ks * 16;
            unsigned a[4][4], b[4][2];
#pragma unroll
            for (int mt = 0; mt < 4; mt++) {
                uint32_t addr = Ab[buf] + (wm * 64 + mt * 16 + (lane & 15)) * A_STRIDE
                              + (kh + (lane >> 4) * 8) * 2;
                ldsm_x4(a[mt][0], a[mt][1], a[mt][2], a[mt][3], addr);
            }
#pragma unroll
            for (int nt2 = 0; nt2 < 2; nt2++) {
                unsigned r0, r1, r2, r3;
                uint32_t addr = Bb[buf] + (kh + (lane & 15)) * B_STRIDE
                              + (wn * 32 + nt2 * 16 + (lane >> 4) * 8) * 2;
                ldsm_x4_t(r0, r1, r2, r3, addr);
                b[nt2 * 2][0] = r0;     b[nt2 * 2][1] = r1;
                b[nt2 * 2 + 1][0] = r2; b[nt2 * 2 + 1][1] = r3;
            }
#pragma unroll
            for (int mt = 0; mt < 4; mt++)
#pragma unroll
                for (int nt = 0; nt < 4; nt++)
                    mma_f16(acc[mt][nt], a[mt], b[nt], acc[mt][nt]);
        }
        __syncthreads();
    }
#undef ISSUE

#pragma unroll
    for (int mt = 0; mt < 4; mt++)
#pragma unroll
        for (int nt = 0; nt < 4; nt++) {
            int c = col0 + wn * 32 + nt * 8 + 2 * tq;
#pragma unroll
            for (int half = 0; half < 2; half++) {
                int m = row0 + wm * 64 + mt * 16 + g + half * 8;
                float2 val = make_float2(acc[mt][nt][half * 2], acc[mt][nt][half * 2 + 1]);
                if (MODE == 0) {
                    int bi = m >> 11, n = m & 2047, h = c >> 6, d = c & 63;
                    *(unsigned*)&Yh[(((size_t)(bi * HEADS + h) * SEQ + n) << 6) + d] =
                        f2h2(val.x, val.y);
                } else {
                    float2 bv = *(const float2*)&bo[c];
                    float2 rv = *(const float2*)&resid[(size_t)m * DIMD + c];
                    val.x += bv.x + rv.x;
                    val.y += bv.y + rv.y;
                    *(float2*)&Yf[(size_t)m * DIMD + c] = val;
                }
            }
        }
}

// ---------------- partial RoPE (fp16 data, f32 math) ----------------
__global__ void rope_kernel(const float* __restrict__ rope) {
    int idx = blockIdx.x * blockDim.x + threadIdx.x;
    if (idx >= BH * SEQ * 16) return;
    int p = idx & 15;
    int n = (idx >> 4) & (SEQ - 1);
    int z = idx >> 15;
    size_t base = ((size_t)z * SEQ + n) * DH;
    float r1 = rope[n * ROT + p];
    float r2 = rope[n * ROT + p + 16];
    float c1 = cosf(r1), s1 = sinf(r1);
    float c2 = cosf(r2), s2 = sinf(r2);
    __half* arrs[3] = {g_Q, g_K, g_V};
#pragma unroll
    for (int a = 0; a < 3; a++) {
        float t0 = __half2float(arrs[a][base + p]);
        float t1 = __half2float(arrs[a][base + p + 16]);
        arrs[a][base + p]      = __float2half(t0 * c1 - t1 * s1);
        arrs[a][base + p + 16] = __float2half(t1 * c2 + t0 * s2);
    }
}

// ===== fused flash attention: i64 x j64, 256 thr, 4(m)x2(n), 2 CTA/SM ======
#define RB 144
#define KVB 9216    // one 64-row tile buffer
__global__ __launch_bounds__(256, 2) void fused_attn(float* __restrict__ S) {
    extern __shared__ char smraw[];
    uint32_t sb = smem_u32(smraw);
    uint32_t qb = sb;                       // 9216
    uint32_t kb0 = sb + KVB;                // 2 x 9216
    uint32_t vb0 = sb + 3 * KVB;            // 2 x 9216
    float* inv_s     = (float*)(smraw + 5 * KVB);              // 256 B
    float (*part)[2] = (float (*)[2])(smraw + 5 * KVB + 256);  // 512 B
    float (*obuf)[66] = (float (*)[66])smraw;                  // overlay 16896 B

    int t = threadIdx.x;
    int w = t >> 5, lane = t & 31, g = lane >> 2, tq = lane & 3;
    int wm = w & 3, wn = w >> 2;            // 4 m x 2 n
    int z = blockIdx.y;
    int i0 = blockIdx.x * 64;
    const __half* Qb = g_Q + (size_t)z * SEQ * DH;
    const __half* Kb = g_K + (size_t)z * SEQ * DH;
    const __half* Vb = g_V + (size_t)z * SEQ * DH;
    float* Sb = S + (size_t)z * SEQ * SEQ;

    // 2 chunks/thread: 512 chunks per 64x64-half tile (8 chunks per 128B row)
    int crow[2], cch[2];
#pragma unroll
    for (int s = 0; s < 2; s++) {
        int idx = t + s * 256;
        crow[s] = idx >> 3; cch[s] = (idx & 7) * 16;
    }

    // ---- issue Q + K(0) ----
#pragma unroll
    for (int s = 0; s < 2; s++) {
        CPA16(qb + crow[s] * RB + cch[s],
              (const char*)(Qb + (size_t)(i0 + crow[s]) * DH) + cch[s]);
        CPA16(kb0 + crow[s] * RB + cch[s],
              (const char*)(Kb + (size_t)crow[s] * DH) + cch[s]);
    }
    CPA_COMMIT();

    int mrb = wm * 16;
    int aro = lane & 15;
    int akh = (lane >> 4) * 16;

    // ======== PASS 1: row sums ========
    float rsum[2] = {0.f, 0.f};

    for (int p = 0; p < 32; p++) {
        uint32_t kcur = kb0 + (p & 1) * KVB;
        if (p + 1 < 32) {
            uint32_t kdst = kb0 + ((p + 1) & 1) * KVB;
            const __half* ksrc = Kb + (size_t)(p + 1) * 64 * DH;
#pragma unroll
            for (int s = 0; s < 2; s++)
                CPA16(kdst + crow[s] * RB + cch[s],
                      (const char*)(ksrc + (size_t)crow[s] * DH) + cch[s]);
            CPA_COMMIT();
            CPA_WAIT(1);
        } else {
            CPA_WAIT(0);
        }
        __syncthreads();

        float acc[4][4];
#pragma unroll
        for (int i = 0; i < 4; i++)
#pragma unroll
            for (int r = 0; r < 4; r++) acc[i][r] = 0.f;

#pragma unroll
        for (int kc = 0; kc < 4; kc++) {
            unsigned a[4], b[4][2];
            ldsm_x4(a[0], a[1], a[2], a[3],
                    qb + (mrb + aro) * RB + kc * 32 + akh);
#pragma unroll
            for (int nt2 = 0; nt2 < 2; nt2++) {
                unsigned r0, r1, r2, r3;
                ldsm_x4(r0, r1, r2, r3,
                        kcur + (wn * 32 + nt2 * 16 + aro) * RB + kc * 32 + akh);
                b[2 * nt2][0] = r0;     b[2 * nt2][1] = r2;
                b[2 * nt2 + 1][0] = r1; b[2 * nt2 + 1][1] = r3;
            }
#pragma unroll
            for (int nt = 0; nt < 4; nt++)
                mma_f16(acc[nt], a, b[nt], acc[nt]);
        }
#pragma unroll
        for (int nt = 0; nt < 4; nt++) {
            rsum[0] += __expf(acc[nt][0] * 0.125f) + __expf(acc[nt][1] * 0.125f);
            rsum[1] += __expf(acc[nt][2] * 0.125f) + __expf(acc[nt][3] * 0.125f);
        }
        __syncthreads();
    }

#pragma unroll
    for (int half = 0; half < 2; half++) {
        float r = rsum[half];
        r += __shfl_xor_sync(0xffffffffu, r, 1);
        r += __shfl_xor_sync(0xffffffffu, r, 2);
        if (tq == 0) part[mrb + half * 8 + g][wn] = r;
    }
    __syncthreads();
    if (t < 64) inv_s[t] = 1.f / (part[t][0] + part[t][1]);

    // ---- issue K(0)+V(0) for pass 2 ----
#pragma unroll
    for (int s = 0; s < 2; s++) {
        CPA16(kb0 + crow[s] * RB + cch[s],
              (const char*)(Kb + (size_t)crow[s] * DH) + cch[s]);
        CPA16(vb0 + crow[s] * RB + cch[s],
              (const char*)(Vb + (size_t)crow[s] * DH) + cch[s]);
    }
    CPA_COMMIT();

    // ======== PASS 2 ========
    float accO[8][4];
#pragma unroll
    for (int i = 0; i < 8; i++)
#pragma unroll
        for (int r = 0; r < 4; r++) accO[i][r] = 0.f;

    for (int p = 0; p < 32; p++) {
        uint32_t kcur = kb0 + (p & 1) * KVB;
        uint32_t vcur = vb0 + (p & 1) * KVB;
        if (p + 1 < 32) {
            uint32_t kdst = kb0 + ((p + 1) & 1) * KVB;
            uint32_t vdst = vb0 + ((p + 1) & 1) * KVB;
            const __half* ksrc = Kb + (size_t)(p + 1) * 64 * DH;
            const __half* vsrc = Vb + (size_t)(p + 1) * 64 * DH;
#pragma unroll
            for (int s = 0; s < 2; s++) {
                CPA16(kdst + crow[s] * RB + cch[s],
                      (const char*)(ksrc + (size_t)crow[s] * DH) + cch[s]);
                CPA16(vdst + crow[s] * RB + cch[s],
                      (const char*)(vsrc + (size_t)crow[s] * DH) + cch[s]);
            }
            CPA_COMMIT();
            CPA_WAIT(1);
        } else {
            CPA_WAIT(0);
        }
        __syncthreads();

        float acc[4][4];
#pragma unroll
        for (int i = 0; i < 4; i++)
#pragma unroll
            for (int r = 0; r < 4; r++) acc[i][r] = 0.f;

#pragma unroll
        for (int kc = 0; kc < 4; kc++) {
            unsigned a[4], b[4][2];
            ldsm_x4(a[0], a[1], a[2], a[3],
                    qb + (mrb + aro) * RB + kc * 32 + akh);
#pragma unroll
            for (int nt2 = 0; nt2 < 2; nt2++) {
                unsigned r0, r1, r2, r3;
                ldsm_x4(r0, r1, r2, r3,
                        kcur + (wn * 32 + nt2 * 16 + aro) * RB + kc * 32 + akh);
                b[2 * nt2][0] = r0;     b[2 * nt2][1] = r2;
                b[2 * nt2 + 1][0] = r1; b[2 * nt2 + 1][1] = r3;
            }
#pragma unroll
            for (int nt = 0; nt < 4; nt++)
                mma_f16(acc[nt], a, b[nt], acc[nt]);
        }

        int j0 = p * 64;
        int mr0 = mrb + g;
        float iv0 = inv_s[mr0];
        float iv1 = inv_s[mr0 + 8];
#pragma unroll
        for (int nt = 0; nt < 4; nt++) {
            acc[nt][0] = __expf(acc[nt][0] * 0.125f) * iv0;
            acc[nt][1] = __expf(acc[nt][1] * 0.125f) * iv0;
            acc[nt][2] = __expf(acc[nt][2] * 0.125f) * iv1;
            acc[nt][3] = __expf(acc[nt][3] * 0.125f) * iv1;
            int c = j0 + wn * 32 + nt * 8 + 2 * tq;
            stcs2(&Sb[(size_t)(i0 + mr0) * SEQ + c],     acc[nt][0], acc[nt][1]);
            stcs2(&Sb[(size_t)(i0 + mr0 + 8) * SEQ + c], acc[nt][2], acc[nt][3]);
        }

        // PV over warp's 32-col k-slice
#pragma unroll
        for (int s = 0; s < 2; s++) {
            unsigned aP[4];
            aP[0] = f2h2(acc[2*s][0],   acc[2*s][1]);
            aP[1] = f2h2(acc[2*s][2],   acc[2*s][3]);
            aP[2] = f2h2(acc[2*s+1][0], acc[2*s+1][1]);
            aP[3] = f2h2(acc[2*s+1][2], acc[2*s+1][3]);
#pragma unroll
            for (int nt2 = 0; nt2 < 4; nt2++) {
                unsigned r0, r1, r2, r3;
                ldsm_x4_t(r0, r1, r2, r3,
                          vcur + (wn * 32 + s * 16 + aro) * RB
                               + (nt2 * 16 + (lane >> 4) * 8) * 2);
                unsigned b0[2] = {r0, r1}, b1[2] = {r2, r3};
                mma_f16(accO[2*nt2],     aP, b0, accO[2*nt2]);
                mma_f16(accO[2*nt2 + 1], aP, b1, accO[2*nt2 + 1]);
            }
        }
        __syncthreads();
    }

    // ---- cross-warp O reduce (over wn: 2 partners) ----
    __syncthreads();
#pragma unroll
    for (int p = 0; p < 2; p++) {
        if (wn == p) {
            int r0 = mrb + g;
#pragma unroll
            for (int nt = 0; nt < 8; nt++) {
                int c = nt * 8 + 2 * tq;
                if (p == 0) {
                    *(float2*)&obuf[r0][c]     = make_float2(accO[nt][0], accO[nt][1]);
                    *(float2*)&obuf[r0 + 8][c] = make_float2(accO[nt][2], accO[nt][3]);
                } else {
                    float2 o0 = *(float2*)&obuf[r0][c];
                    float2 o1 = *(float2*)&obuf[r0 + 8][c];
                    o0.x += accO[nt][0]; o0.y += accO[nt][1];
                    o1.x += accO[nt][2]; o1.y += accO[nt][3];
                    *(float2*)&obuf[r0][c] = o0;
                    *(float2*)&obuf[r0 + 8][c] = o1;
                }
            }
        }
        __syncthreads();
    }

    // write O (half): [b, n, h*64+d]   64 rows x 64 cols
    int bi = z >> 4, h = z & 15;
#pragma unroll
    for (int it = 0; it < 4; it++) {
        int idx = t + it * 256;
        int m = idx >> 4, c4 = (idx & 15) * 4;
        uint2 v = make_uint2(f2h2(obuf[m][c4], obuf[m][c4 + 1]),
                             f2h2(obuf[m][c4 + 2], obuf[m][c4 + 3]));
        *(uint2*)&g_O[((size_t)bi * SEQ + i0 + m) * DIMD + h * 64 + c4] = v;
    }
}

// ---------------------------- launcher -------------------------------------
extern "C" void kernel_launch(void* const* d_in, const int* in_sizes, int n_in,
                              void* d_out, int out_size) {
    const float* x    = (const float*)d_in[0];
    const float* rope = (const float*)d_in[1];
    const float* Wq   = (const float*)d_in[2];
    const float* Wk   = (const float*)d_in[3];
    const float* Wv   = (const float*)d_in[4];
    const float* Wo   = (const float*)d_in[5];
    const float* bo   = (const float*)d_in[6];

    float* out  = (float*)d_out;
    float* attn = out + OUT_ELEMS;

    __half *Xp, *Whp, *Op;
    cudaGetSymbolAddress((void**)&Xp,  g_X);
    cudaGetSymbolAddress((void**)&Whp, g_Wh);
    cudaGetSymbolAddress((void**)&Op,  g_O);

    const int FA_SMEM = 5 * 9216 + 256 + 512;   // 46848
    const int GP_SMEM = 37888;
    cudaFuncSetAttribute(fused_attn, cudaFuncAttributeMaxDynamicSharedMemorySize, FA_SMEM);

    convert_half<<<(int)((OUT_ELEMS / 4 + 4 * DIMD * DIMD / 4) / 256), 256>>>(x, Wq, Wk, Wv, Wo);

    gemm_pipe<0><<<dim3(8, 64, 3), 256, GP_SMEM>>>(Xp, Whp, nullptr, nullptr, nullptr);

    rope_kernel<<<(BH * SEQ * 16) / 256, 256>>>(rope);

    fused_attn<<<dim3(32, 64), 256, FA_SMEM>>>(attn);

    gemm_pipe<1><<<dim3(8, 64), 256, GP_SMEM>>>(Op, Whp + 3 * (size_t)DIMD * DIMD, bo, x, out);
}

// round 15
// speedup vs baseline: 1.1062x; 1.1062x over previous
#include <cuda_runtime.h>
#include <cuda_fp16.h>
#include <math.h>
#include <stdint.h>

#define BB     4
#define SEQ    2048
#define DIMD   1024
#define HEADS  16
#define DH     64
#define ROT    32
#define BH     (BB*HEADS)          // 64
#define MROWS  (BB*SEQ)            // 8192
#define OUT_ELEMS ((size_t)MROWS*DIMD)

// ---------------- scratch (fp16) ----------------
__device__ __half g_Q[(size_t)BH*SEQ*DH];
__device__ __half g_K[(size_t)BH*SEQ*DH];
__device__ __half g_V[(size_t)BH*SEQ*DH];
__device__ __half g_O[(size_t)MROWS*DIMD];
__device__ __half g_X[(size_t)MROWS*DIMD];
__device__ __half g_Wh[(size_t)4*DIMD*DIMD];

// ---------------- helpers ----------------
__device__ __forceinline__ unsigned f2h2(float a, float b) {
    unsigned u;
    asm("cvt.rn.f16x2.f32 %0, %2, %1;" : "=r"(u) : "f"(a), "f"(b));
    return u;
}
__device__ __forceinline__ uint32_t smem_u32(const void* p) {
    uint32_t a;
    asm("{ .reg .u64 t; cvta.to.shared.u64 t, %1; cvt.u32.u64 %0, t; }" : "=r"(a) : "l"(p));
    return a;
}
__device__ __forceinline__ void mma_f16(float d[4], const unsigned a[4],
                                        const unsigned b[2], const float c[4]) {
    asm volatile(
        "mma.sync.aligned.m16n8k16.row.col.f32.f16.f16.f32 "
        "{%0,%1,%2,%3}, {%4,%5,%6,%7}, {%8,%9}, {%10,%11,%12,%13};"
        : "=f"(d[0]), "=f"(d[1]), "=f"(d[2]), "=f"(d[3])
        : "r"(a[0]), "r"(a[1]), "r"(a[2]), "r"(a[3]),
          "r"(b[0]), "r"(b[1]),
          "f"(c[0]), "f"(c[1]), "f"(c[2]), "f"(c[3]));
}
__device__ __forceinline__ void ldsm_x4(unsigned& r0, unsigned& r1,
                                        unsigned& r2, unsigned& r3, uint32_t a) {
    asm volatile("ldmatrix.sync.aligned.m8n8.x4.shared.b16 {%0,%1,%2,%3}, [%4];"
                 : "=r"(r0), "=r"(r1), "=r"(r2), "=r"(r3) : "r"(a));
}
__device__ __forceinline__ void ldsm_x4_t(unsigned& r0, unsigned& r1,
                                          unsigned& r2, unsigned& r3, uint32_t a) {
    asm volatile("ldmatrix.sync.aligned.m8n8.x4.trans.shared.b16 {%0,%1,%2,%3}, [%4];"
                 : "=r"(r0), "=r"(r1), "=r"(r2), "=r"(r3) : "r"(a));
}
#define CPA16(d, s)   asm volatile("cp.async.ca.shared.global [%0], [%1], 16;" :: "r"(d), "l"(s))
#define CPA_COMMIT()  asm volatile("cp.async.commit_group;" ::: "memory")
#define CPA_WAIT(n)   asm volatile("cp.async.wait_group %0;" :: "n"(n) : "memory")
__device__ __forceinline__ void stcs2(float* p, float x, float y) {
    asm volatile("st.global.cs.v2.f32 [%0], {%1,%2};" :: "l"(p), "f"(x), "f"(y));
}

// ---------------- f32 -> f16 conversion (x + 4 weights) ----------------
__global__ void convert_half(const float* __restrict__ x,
                             const float* __restrict__ Wq, const float* __restrict__ Wk,
                             const float* __restrict__ Wv, const float* __restrict__ Wo) {
    size_t i = (size_t)blockIdx.x * blockDim.x + threadIdx.x;
    const size_t XN = OUT_ELEMS / 4;
    const size_t WN = (size_t)DIMD * DIMD / 4;
    const float* src; __half* dst; size_t off;
    if (i < XN)                { src = x;  dst = g_X;               off = i; }
    else if (i < XN + WN)      { src = Wq; dst = g_Wh;              off = i - XN; }
    else if (i < XN + 2 * WN)  { src = Wk; dst = g_Wh + WN * 4;     off = i - XN - WN; }
    else if (i < XN + 3 * WN)  { src = Wv; dst = g_Wh + 2 * WN * 4; off = i - XN - 2 * WN; }
    else                       { src = Wo; dst = g_Wh + 3 * WN * 4; off = i - XN - 3 * WN; }
    float4 v = *(const float4*)(src + off * 4);
    *(uint2*)(dst + off * 4) = make_uint2(f2h2(v.x, v.y), f2h2(v.z, v.w));
}

// ============ pipelined fp16 GEMM (cp.async + ldmatrix), 2 CTA/SM ===========
#define A_STRIDE 80
#define B_STRIDE 272
template <int MODE>
__global__ __launch_bounds__(256, 2) void gemm_pipe(
    const __half* __restrict__ Aglob, const __half* __restrict__ Wbase,
    const float* __restrict__ bo, const float* __restrict__ resid,
    float* __restrict__ Yf)
{
    extern __shared__ char sm[];
    uint32_t sb = smem_u32(sm);
    uint32_t Ab[2] = {sb, sb + 10240};
    uint32_t Bb[2] = {sb + 20480, sb + 20480 + 8704};

    int t = threadIdx.x, lane = t & 31, w = t >> 5;
    int g = lane >> 2, tq = lane & 3;
    int wm = w & 1, wn = w >> 1;
    int row0 = blockIdx.y * 128, col0 = blockIdx.x * 128;

    const __half* Bh;
    __half* Yh = nullptr;
    if (MODE == 0) {
        int z = blockIdx.z;
        Bh = Wbase + (size_t)z * DIMD * DIMD;
        Yh = (z == 0) ? g_Q : (z == 1) ? g_K : g_V;
    } else {
        Bh = Wbase;
    }

    float acc[4][4][4];
#pragma unroll
    for (int i = 0; i < 4; i++)
#pragma unroll
        for (int j = 0; j < 4; j++)
#pragma unroll
            for (int r = 0; r < 4; r++) acc[i][j][r] = 0.f;

    int ar[2], ac[2], br[2], bc[2];
#pragma unroll
    for (int s = 0; s < 2; s++) {
        int idx = t + s * 256;
        ar[s] = idx >> 2;  ac[s] = (idx & 3) * 16;
        br[s] = idx >> 4;  bc[s] = (idx & 15) * 16;
    }

#define ISSUE(p) do { \
    int _buf = (p) & 1; int _k0 = (p) * 32; \
    _Pragma("unroll") \
    for (int s = 0; s < 2; s++) { \
        CPA16(Ab[_buf] + ar[s] * A_STRIDE + ac[s], \
              (const char*)(Aglob + (size_t)(row0 + ar[s]) * DIMD + _k0) + ac[s]); \
        CPA16(Bb[_buf] + br[s] * B_STRIDE + bc[s], \
              (const char*)(Bh + (size_t)(_k0 + br[s]) * DIMD + col0) + bc[s]); \
    } \
} while (0)

    ISSUE(0); CPA_COMMIT();

    for (int p = 0; p < 32; p++) {
        if (p + 1 < 32) { ISSUE(p + 1); CPA_COMMIT(); CPA_WAIT(1); }
        else            { CPA_WAIT(0); }
        __syncthreads();
        int buf = p & 1;
#pragma unroll
        for (int ks = 0; ks < 2; ks++) {
            int kh = ks * 16;
            unsigned a[4][4], b[4][2];
#pragma unroll
            for (int mt = 0; mt < 4; mt++) {
                uint32_t addr = Ab[buf] + (wm * 64 + mt * 16 + (lane & 15)) * A_STRIDE
                              + (kh + (lane >> 4) * 8) * 2;
                ldsm_x4(a[mt][0], a[mt][1], a[mt][2], a[mt][3], addr);
            }
#pragma unroll
            for (int nt2 = 0; nt2 < 2; nt2++) {
                unsigned r0, r1, r2, r3;
                uint32_t addr = Bb[buf] + (kh + (lane & 15)) * B_STRIDE
                              + (wn * 32 + nt2 * 16 + (lane >> 4) * 8) * 2;
                ldsm_x4_t(r0, r1, r2, r3, addr);
                b[nt2 * 2][0] = r0;     b[nt2 * 2][1] = r1;
                b[nt2 * 2 + 1][0] = r2; b[nt2 * 2 + 1][1] = r3;
            }
#pragma unroll
            for (int mt = 0; mt < 4; mt++)
#pragma unroll
                for (int nt = 0; nt < 4; nt++)
                    mma_f16(acc[mt][nt], a[mt], b[nt], acc[mt][nt]);
        }
        __syncthreads();
    }
#undef ISSUE

#pragma unroll
    for (int mt = 0; mt < 4; mt++)
#pragma unroll
        for (int nt = 0; nt < 4; nt++) {
            int c = col0 + wn * 32 + nt * 8 + 2 * tq;
#pragma unroll
            for (int half = 0; half < 2; half++) {
                int m = row0 + wm * 64 + mt * 16 + g + half * 8;
                float2 val = make_float2(acc[mt][nt][half * 2], acc[mt][nt][half * 2 + 1]);
                if (MODE == 0) {
                    int bi = m >> 11, n = m & 2047, h = c >> 6, d = c & 63;
                    *(unsigned*)&Yh[(((size_t)(bi * HEADS + h) * SEQ + n) << 6) + d] =
                        f2h2(val.x, val.y);
                } else {
                    float2 bv = *(const float2*)&bo[c];
                    float2 rv = *(const float2*)&resid[(size_t)m * DIMD + c];
                    val.x += bv.x + rv.x;
                    val.y += bv.y + rv.y;
                    *(float2*)&Yf[(size_t)m * DIMD + c] = val;
                }
            }
        }
}

// ---------------- partial RoPE (fp16 data, f32 math) ----------------
__global__ void rope_kernel(const float* __restrict__ rope) {
    int idx = blockIdx.x * blockDim.x + threadIdx.x;
    if (idx >= BH * SEQ * 16) return;
    int p = idx & 15;
    int n = (idx >> 4) & (SEQ - 1);
    int z = idx >> 15;
    size_t base = ((size_t)z * SEQ + n) * DH;
    float r1 = rope[n * ROT + p];
    float r2 = rope[n * ROT + p + 16];
    float c1 = cosf(r1), s1 = sinf(r1);
    float c2 = cosf(r2), s2 = sinf(r2);
    __half* arrs[3] = {g_Q, g_K, g_V};
#pragma unroll
    for (int a = 0; a < 3; a++) {
        float t0 = __half2float(arrs[a][base + p]);
        float t1 = __half2float(arrs[a][base + p + 16]);
        arrs[a][base + p]      = __float2half(t0 * c1 - t1 * s1);
        arrs[a][base + p + 16] = __float2half(t1 * c2 + t0 * s2);
    }
}

// ===== fused flash attention: 256 threads, 4(m)x2(n), ldmatrix frags =======
#define RB 144
__global__ __launch_bounds__(256) void fused_attn(float* __restrict__ S) {
    extern __shared__ char smraw[];
    uint32_t sb = smem_u32(smraw);
    uint32_t qb = sb, kb0 = sb + 18432, vb0 = sb + 55296;
    float* inv_s        = (float*)(smraw + 92160);
    float (*part)[2]    = (float (*)[2])(smraw + 92672);
    float (*obuf)[66]   = (float (*)[66])smraw;

    int t = threadIdx.x;
    int w = t >> 5, lane = t & 31, g = lane >> 2, tq = lane & 3;
    int wm = w & 3, wn = w >> 2;        // 4 m-groups x 2 n-groups
    int z = blockIdx.y;
    int i0 = blockIdx.x * 128;
    const __half* Qb = g_Q + (size_t)z * SEQ * DH;
    const __half* Kb = g_K + (size_t)z * SEQ * DH;
    const __half* Vb = g_V + (size_t)z * SEQ * DH;
    float* Sb = S + (size_t)z * SEQ * SEQ;

    int crow[4], cch[4];
#pragma unroll
    for (int s = 0; s < 4; s++) {
        int idx = t + s * 256;
        crow[s] = idx >> 3; cch[s] = (idx & 7) * 16;
    }

#pragma unroll
    for (int s = 0; s < 4; s++) {
        CPA16(qb + crow[s] * RB + cch[s],
              (const char*)(Qb + (size_t)(i0 + crow[s]) * DH) + cch[s]);
        CPA16(kb0 + crow[s] * RB + cch[s],
              (const char*)(Kb + (size_t)crow[s] * DH) + cch[s]);
    }
    CPA_COMMIT();

    int mrb = wm * 32;
    int aro = (lane & 15);
    int akh = (lane >> 4) * 16;

    // ======== PASS 1: row sums ========
    float rsum[2][2];
    rsum[0][0] = rsum[0][1] = rsum[1][0] = rsum[1][1] = 0.f;

    for (int p = 0; p < 16; p++) {
        uint32_t kcur = kb0 + (p & 1) * 18432;
        if (p + 1 < 16) {
            uint32_t kdst = kb0 + ((p + 1) & 1) * 18432;
            const __half* ksrc = Kb + (size_t)(p + 1) * 128 * DH;
#pragma unroll
            for (int s = 0; s < 4; s++)
                CPA16(kdst + crow[s] * RB + cch[s],
                      (const char*)(ksrc + (size_t)crow[s] * DH) + cch[s]);
            CPA_COMMIT();
            CPA_WAIT(1);
        } else {
            CPA_WAIT(0);
        }
        __syncthreads();

        float acc[2][8][4];
#pragma unroll
        for (int i = 0; i < 2; i++)
#pragma unroll
            for (int j = 0; j < 8; j++)
#pragma unroll
                for (int r = 0; r < 4; r++) acc[i][j][r] = 0.f;

#pragma unroll
        for (int kc = 0; kc < 4; kc++) {
            unsigned a[2][4], b[8][2];
#pragma unroll
            for (int mt = 0; mt < 2; mt++)
                ldsm_x4(a[mt][0], a[mt][1], a[mt][2], a[mt][3],
                        qb + (mrb + mt * 16 + aro) * RB + kc * 32 + akh);
#pragma unroll
            for (int nt2 = 0; nt2 < 4; nt2++) {
                unsigned r0, r1, r2, r3;
                ldsm_x4(r0, r1, r2, r3,
                        kcur + (wn * 64 + nt2 * 16 + aro) * RB + kc * 32 + akh);
                b[2 * nt2][0] = r0;     b[2 * nt2][1] = r2;
                b[2 * nt2 + 1][0] = r1; b[2 * nt2 + 1][1] = r3;
            }
#pragma unroll
            for (int mt = 0; mt < 2; mt++)
#pragma unroll
                for (int nt = 0; nt < 8; nt++)
                    mma_f16(acc[mt][nt], a[mt], b[nt], acc[mt][nt]);
        }
#pragma unroll
        for (int mt = 0; mt < 2; mt++)
#pragma unroll
            for (int nt = 0; nt < 8; nt++) {
                rsum[mt][0] += __expf(acc[mt][nt][0] * 0.125f) + __expf(acc[mt][nt][1] * 0.125f);
                rsum[mt][1] += __expf(acc[mt][nt][2] * 0.125f) + __expf(acc[mt][nt][3] * 0.125f);
            }
        __syncthreads();
    }

#pragma unroll
    for (int mt = 0; mt < 2; mt++)
#pragma unroll
        for (int half = 0; half < 2; half++) {
            float r = rsum[mt][half];
            r += __shfl_xor_sync(0xffffffffu, r, 1);
            r += __shfl_xor_sync(0xffffffffu, r, 2);
            if (tq == 0) part[mrb + mt * 16 + half * 8 + g][wn] = r;
        }
    __syncthreads();
    if (t < 128) inv_s[t] = 1.f / (part[t][0] + part[t][1]);

#pragma unroll
    for (int s = 0; s < 4; s++) {
        CPA16(kb0 + crow[s] * RB + cch[s],
              (const char*)(Kb + (size_t)crow[s] * DH) + cch[s]);
        CPA16(vb0 + crow[s] * RB + cch[s],
              (const char*)(Vb + (size_t)crow[s] * DH) + cch[s]);
    }
    CPA_COMMIT();

    // ======== PASS 2 ========
    float accO[2][8][4];
#pragma unroll
    for (int i = 0; i < 2; i++)
#pragma unroll
        for (int j = 0; j < 8; j++)
#pragma unroll
            for (int r = 0; r < 4; r++) accO[i][j][r] = 0.f;

    for (int p = 0; p < 16; p++) {
        uint32_t kcur = kb0 + (p & 1) * 18432;
        uint32_t vcur = vb0 + (p & 1) * 18432;
        if (p + 1 < 16) {
            uint32_t kdst = kb0 + ((p + 1) & 1) * 18432;
            uint32_t vdst = vb0 + ((p + 1) & 1) * 18432;
            const __half* ksrc = Kb + (size_t)(p + 1) * 128 * DH;
            const __half* vsrc = Vb + (size_t)(p + 1) * 128 * DH;
#pragma unroll
            for (int s = 0; s < 4; s++) {
                CPA16(kdst + crow[s] * RB + cch[s],
                      (const char*)(ksrc + (size_t)crow[s] * DH) + cch[s]);
                CPA16(vdst + crow[s] * RB + cch[s],
                      (const char*)(vsrc + (size_t)crow[s] * DH) + cch[s]);
            }
            CPA_COMMIT();
            CPA_WAIT(1);
        } else {
            CPA_WAIT(0);
        }
        __syncthreads();

        float acc[2][8][4];
#pragma unroll
        for (int i = 0; i < 2; i++)
#pragma unroll
            for (int j = 0; j < 8; j++)
#pragma unroll
                for (int r = 0; r < 4; r++) acc[i][j][r] = 0.f;

#pragma unroll
        for (int kc = 0; kc < 4; kc++) {
            unsigned a[2][4], b[8][2];
#pragma unroll
            for (int mt = 0; mt < 2; mt++)
                ldsm_x4(a[mt][0], a[mt][1], a[mt][2], a[mt][3],
                        qb + (mrb + mt * 16 + aro) * RB + kc * 32 + akh);
#pragma unroll
            for (int nt2 = 0; nt2 < 4; nt2++) {
                unsigned r0, r1, r2, r3;
                ldsm_x4(r0, r1, r2, r3,
                        kcur + (wn * 64 + nt2 * 16 + aro) * RB + kc * 32 + akh);
                b[2 * nt2][0] = r0;     b[2 * nt2][1] = r2;
                b[2 * nt2 + 1][0] = r1; b[2 * nt2 + 1][1] = r3;
            }
#pragma unroll
            for (int mt = 0; mt < 2; mt++)
#pragma unroll
                for (int nt = 0; nt < 8; nt++)
                    mma_f16(acc[mt][nt], a[mt], b[nt], acc[mt][nt]);
        }

        int j0 = p * 128;
#pragma unroll
        for (int mt = 0; mt < 2; mt++) {
            int mr0 = mrb + mt * 16 + g;
            float iv0 = inv_s[mr0];
            float iv1 = inv_s[mr0 + 8];
#pragma unroll
            for (int nt = 0; nt < 8; nt++) {
                acc[mt][nt][0] = __expf(acc[mt][nt][0] * 0.125f) * iv0;
                acc[mt][nt][1] = __expf(acc[mt][nt][1] * 0.125f) * iv0;
                acc[mt][nt][2] = __expf(acc[mt][nt][2] * 0.125f) * iv1;
                acc[mt][nt][3] = __expf(acc[mt][nt][3] * 0.125f) * iv1;
                int c = j0 + wn * 64 + nt * 8 + 2 * tq;
                stcs2(&Sb[(size_t)(i0 + mr0) * SEQ + c],     acc[mt][nt][0], acc[mt][nt][1]);
                stcs2(&Sb[(size_t)(i0 + mr0 + 8) * SEQ + c], acc[mt][nt][2], acc[mt][nt][3]);
            }
        }

        // PV over warp's 64-col k-slice (4 chunks of k16)
#pragma unroll
        for (int s = 0; s < 4; s++) {
            unsigned bV[8][2];
#pragma unroll
            for (int nt2 = 0; nt2 < 4; nt2++) {
                unsigned r0, r1, r2, r3;
                ldsm_x4_t(r0, r1, r2, r3,
                          vcur + (wn * 64 + s * 16 + aro) * RB
                               + (nt2 * 16 + (lane >> 4) * 8) * 2);
                bV[2 * nt2][0] = r0;     bV[2 * nt2][1] = r1;
                bV[2 * nt2 + 1][0] = r2; bV[2 * nt2 + 1][1] = r3;
            }
#pragma unroll
            for (int mt = 0; mt < 2; mt++) {
                unsigned aP[4];
                aP[0] = f2h2(acc[mt][2*s][0],   acc[mt][2*s][1]);
                aP[1] = f2h2(acc[mt][2*s][2],   acc[mt][2*s][3]);
                aP[2] = f2h2(acc[mt][2*s+1][0], acc[mt][2*s+1][1]);
                aP[3] = f2h2(acc[mt][2*s+1][2], acc[mt][2*s+1][3]);
#pragma unroll
                for (int nt = 0; nt < 8; nt++)
                    mma_f16(accO[mt][nt], aP, bV[nt], accO[mt][nt]);
            }
        }
        __syncthreads();
    }

    // ---- cross-warp O reduce (over wn: 2 partners) ----
    __syncthreads();
#pragma unroll
    for (int p = 0; p < 2; p++) {
        if (wn == p) {
#pragma unroll
            for (int mt = 0; mt < 2; mt++) {
                int r0 = mrb + mt * 16 + g;
#pragma unroll
                for (int nt = 0; nt < 8; nt++) {
                    int c = nt * 8 + 2 * tq;
                    if (p == 0) {
                        *(float2*)&obuf[r0][c]     = make_float2(accO[mt][nt][0], accO[mt][nt][1]);
                        *(float2*)&obuf[r0 + 8][c] = make_float2(accO[mt][nt][2], accO[mt][nt][3]);
                    } else {
                        float2 o0 = *(float2*)&obuf[r0][c];
                        float2 o1 = *(float2*)&obuf[r0 + 8][c];
                        o0.x += accO[mt][nt][0]; o0.y += accO[mt][nt][1];
                        o1.x += accO[mt][nt][2]; o1.y += accO[mt][nt][3];
                        *(float2*)&obuf[r0][c] = o0;
                        *(float2*)&obuf[r0 + 8][c] = o1;
                    }
                }
            }
        }
        __syncthreads();
    }

    // write O (half): [b, n, h*64+d]
    int bi = z >> 4, h = z & 15;
#pragma unroll
    for (int it = 0; it < 8; it++) {
        int idx = t + it * 256;
        int m = idx >> 4, c4 = (idx & 15) * 4;
        uint2 v = make_uint2(f2h2(obuf[m][c4], obuf[m][c4 + 1]),
                             f2h2(obuf[m][c4 + 2], obuf[m][c4 + 3]));
        *(uint2*)&g_O[((size_t)bi * SEQ + i0 + m) * DIMD + h * 64 + c4] = v;
    }
}

// ---------------------------- launcher -------------------------------------
extern "C" void kernel_launch(void* const* d_in, const int* in_sizes, int n_in,
                              void* d_out, int out_size) {
    const float* x    = (const float*)d_in[0];
    const float* rope = (const float*)d_in[1];
    const float* Wq   = (const float*)d_in[2];
    const float* Wk   = (const float*)d_in[3];
    const float* Wv   = (const float*)d_in[4];
    const float* Wo   = (const float*)d_in[5];
    const float* bo   = (const float*)d_in[6];

    float* out  = (float*)d_out;
    float* attn = out + OUT_ELEMS;

    __half *Xp, *Whp, *Op;
    cudaGetSymbolAddress((void**)&Xp,  g_X);
    cudaGetSymbolAddress((void**)&Whp, g_Wh);
    cudaGetSymbolAddress((void**)&Op,  g_O);

    const int FA_SMEM = 93696;
    const int GP_SMEM = 37888;
    cudaFuncSetAttribute(fused_attn, cudaFuncAttributeMaxDynamicSharedMemorySize, FA_SMEM);

    convert_half<<<(int)((OUT_ELEMS / 4 + 4 * DIMD * DIMD / 4) / 256), 256>>>(x, Wq, Wk, Wv, Wo);

    gemm_pipe<0><<<dim3(8, 64, 3), 256, GP_SMEM>>>(Xp, Whp, nullptr, nullptr, nullptr);

    rope_kernel<<<(BH * SEQ * 16) / 256, 256>>>(rope);

    fused_attn<<<dim3(16, 64), 256, FA_SMEM>>>(attn);

    gemm_pipe<1><<<dim3(8, 64), 256, GP_SMEM>>>(Op, Whp + 3 * (size_t)DIMD * DIMD, bo, x, out);
}

// round 16
// speedup vs baseline: 1.1377x; 1.0285x over previous
#include <cuda_runtime.h>
#include <cuda_fp16.h>
#include <math.h>
#include <stdint.h>

#define BB     4
#define SEQ    2048
#define DIMD   1024
#define HEADS  16
#define DH     64
#define ROT    32
#define BH     (BB*HEADS)          // 64
#define MROWS  (BB*SEQ)            // 8192
#define OUT_ELEMS ((size_t)MROWS*DIMD)

// ---------------- scratch (fp16) ----------------
__device__ __half g_Q[(size_t)BH*SEQ*DH];
__device__ __half g_K[(size_t)BH*SEQ*DH];
__device__ __half g_V[(size_t)BH*SEQ*DH];
__device__ __half g_O[(size_t)MROWS*DIMD];
__device__ __half g_X[(size_t)MROWS*DIMD];
__device__ __half g_Wh[(size_t)4*DIMD*DIMD];

// ---------------- helpers ----------------
__device__ __forceinline__ unsigned f2h2(float a, float b) {
    unsigned u;
    asm("cvt.rn.f16x2.f32 %0, %2, %1;" : "=r"(u) : "f"(a), "f"(b));
    return u;
}
__device__ __forceinline__ uint32_t smem_u32(const void* p) {
    uint32_t a;
    asm("{ .reg .u64 t; cvta.to.shared.u64 t, %1; cvt.u32.u64 %0, t; }" : "=r"(a) : "l"(p));
    return a;
}
__device__ __forceinline__ void mma_f16(float d[4], const unsigned a[4],
                                        const unsigned b[2], const float c[4]) {
    asm volatile(
        "mma.sync.aligned.m16n8k16.row.col.f32.f16.f16.f32 "
        "{%0,%1,%2,%3}, {%4,%5,%6,%7}, {%8,%9}, {%10,%11,%12,%13};"
        : "=f"(d[0]), "=f"(d[1]), "=f"(d[2]), "=f"(d[3])
        : "r"(a[0]), "r"(a[1]), "r"(a[2]), "r"(a[3]),
          "r"(b[0]), "r"(b[1]),
          "f"(c[0]), "f"(c[1]), "f"(c[2]), "f"(c[3]));
}
__device__ __forceinline__ void ldsm_x4(unsigned& r0, unsigned& r1,
                                        unsigned& r2, unsigned& r3, uint32_t a) {
    asm volatile("ldmatrix.sync.aligned.m8n8.x4.shared.b16 {%0,%1,%2,%3}, [%4];"
                 : "=r"(r0), "=r"(r1), "=r"(r2), "=r"(r3) : "r"(a));
}
__device__ __forceinline__ void ldsm_x4_t(unsigned& r0, unsigned& r1,
                                          unsigned& r2, unsigned& r3, uint32_t a) {
    asm volatile("ldmatrix.sync.aligned.m8n8.x4.trans.shared.b16 {%0,%1,%2,%3}, [%4];"
                 : "=r"(r0), "=r"(r1), "=r"(r2), "=r"(r3) : "r"(a));
}
#define CPA16(d, s)   asm volatile("cp.async.ca.shared.global [%0], [%1], 16;" :: "r"(d), "l"(s))
#define CPA_COMMIT()  asm volatile("cp.async.commit_group;" ::: "memory")
#define CPA_WAIT(n)   asm volatile("cp.async.wait_group %0;" :: "n"(n) : "memory")
__device__ __forceinline__ void stcs2(float* p, float x, float y) {
    asm volatile("st.global.cs.v2.f32 [%0], {%1,%2};" :: "l"(p), "f"(x), "f"(y));
}

// ---------------- f32 -> f16 conversion (x + 4 weights) ----------------
__global__ void convert_half(const float* __restrict__ x,
                             const float* __restrict__ Wq, const float* __restrict__ Wk,
                             const float* __restrict__ Wv, const float* __restrict__ Wo) {
    size_t i = (size_t)blockIdx.x * blockDim.x + threadIdx.x;
    const size_t XN = OUT_ELEMS / 4;
    const size_t WN = (size_t)DIMD * DIMD / 4;
    const float* src; __half* dst; size_t off;
    if (i < XN)                { src = x;  dst = g_X;               off = i; }
    else if (i < XN + WN)      { src = Wq; dst = g_Wh;              off = i - XN; }
    else if (i < XN + 2 * WN)  { src = Wk; dst = g_Wh + WN * 4;     off = i - XN - WN; }
    else if (i < XN + 3 * WN)  { src = Wv; dst = g_Wh + 2 * WN * 4; off = i - XN - 2 * WN; }
    else                       { src = Wo; dst = g_Wh + 3 * WN * 4; off = i - XN - 3 * WN; }
    float4 v = *(const float4*)(src + off * 4);
    *(uint2*)(dst + off * 4) = make_uint2(f2h2(v.x, v.y), f2h2(v.z, v.w));
}

// ============ pipelined fp16 GEMM (cp.async + ldmatrix), 2 CTA/SM ===========
// MODE 0: proj q/k/v, head-major half out, rope fused in epilogue.
// MODE 1: final (f32 out + bias + resid)
#define A_STRIDE 80
#define B_STRIDE 272
template <int MODE>
__global__ __launch_bounds__(256, 2) void gemm_pipe(
    const __half* __restrict__ Aglob, const __half* __restrict__ Wbase,
    const float* __restrict__ bo, const float* __restrict__ resid,
    const float* __restrict__ ropet, float* __restrict__ Yf)
{
    extern __shared__ char sm[];
    uint32_t sb = smem_u32(sm);
    uint32_t Ab[2] = {sb, sb + 10240};
    uint32_t Bb[2] = {sb + 20480, sb + 20480 + 8704};

    int t = threadIdx.x, lane = t & 31, w = t >> 5;
    int g = lane >> 2, tq = lane & 3;
    int wm = w & 1, wn = w >> 1;
    int row0 = blockIdx.y * 128, col0 = blockIdx.x * 128;

    const __half* Bh;
    __half* Yh = nullptr;
    if (MODE == 0) {
        int z = blockIdx.z;
        Bh = Wbase + (size_t)z * DIMD * DIMD;
        Yh = (z == 0) ? g_Q : (z == 1) ? g_K : g_V;
    } else {
        Bh = Wbase;
    }

    float acc[4][4][4];
#pragma unroll
    for (int i = 0; i < 4; i++)
#pragma unroll
        for (int j = 0; j < 4; j++)
#pragma unroll
            for (int r = 0; r < 4; r++) acc[i][j][r] = 0.f;

    int ar[2], ac[2], br[2], bc[2];
#pragma unroll
    for (int s = 0; s < 2; s++) {
        int idx = t + s * 256;
        ar[s] = idx >> 2;  ac[s] = (idx & 3) * 16;
        br[s] = idx >> 4;  bc[s] = (idx & 15) * 16;
    }

#define ISSUE(p) do { \
    int _buf = (p) & 1; int _k0 = (p) * 32; \
    _Pragma("unroll") \
    for (int s = 0; s < 2; s++) { \
        CPA16(Ab[_buf] + ar[s] * A_STRIDE + ac[s], \
              (const char*)(Aglob + (size_t)(row0 + ar[s]) * DIMD + _k0) + ac[s]); \
        CPA16(Bb[_buf] + br[s] * B_STRIDE + bc[s], \
              (const char*)(Bh + (size_t)(_k0 + br[s]) * DIMD + col0) + bc[s]); \
    } \
} while (0)

    ISSUE(0); CPA_COMMIT();

    for (int p = 0; p < 32; p++) {
        if (p + 1 < 32) { ISSUE(p + 1); CPA_COMMIT(); CPA_WAIT(1); }
        else            { CPA_WAIT(0); }
        __syncthreads();
        int buf = p & 1;
#pragma unroll
        for (int ks = 0; ks < 2; ks++) {
            int kh = ks * 16;
            unsigned a[4][4], b[4][2];
#pragma unroll
            for (int mt = 0; mt < 4; mt++) {
                uint32_t addr = Ab[buf] + (wm * 64 + mt * 16 + (lane & 15)) * A_STRIDE
                              + (kh + (lane >> 4) * 8) * 2;
                ldsm_x4(a[mt][0], a[mt][1], a[mt][2], a[mt][3], addr);
            }
#pragma unroll
            for (int nt2 = 0; nt2 < 2; nt2++) {
                unsigned r0, r1, r2, r3;
                uint32_t addr = Bb[buf] + (kh + (lane & 15)) * B_STRIDE
                              + (wn * 32 + nt2 * 16 + (lane >> 4) * 8) * 2;
                ldsm_x4_t(r0, r1, r2, r3, addr);
                b[nt2 * 2][0] = r0;     b[nt2 * 2][1] = r1;
                b[nt2 * 2 + 1][0] = r2; b[nt2 * 2 + 1][1] = r3;
            }
#pragma unroll
            for (int mt = 0; mt < 4; mt++)
#pragma unroll
                for (int nt = 0; nt < 4; nt++)
                    mma_f16(acc[mt][nt], a[mt], b[nt], acc[mt][nt]);
        }
        __syncthreads();
    }
#undef ISSUE

    // ---- fused partial RoPE (MODE 0, warps covering head-dims [0,32)) ----
    if (MODE == 0 && (wn & 1) == 0) {
#pragma unroll
        for (int mt = 0; mt < 4; mt++) {
#pragma unroll
            for (int pp = 0; pp < 2; pp++) {     // nt pair (pp, pp+2) <-> (d, d+16)
#pragma unroll
                for (int k = 0; k < 4; k++) {
                    int m = row0 + wm * 64 + mt * 16 + g + (k >> 1) * 8;
                    int n = m & (SEQ - 1);
                    int d = pp * 8 + 2 * tq + (k & 1);   // < 16
                    float ang = ropet[n * ROT + d];
                    float cs, sn;
                    __sincosf(ang, &sn, &cs);
                    // note: __sincosf(x, &s, &c)
                    float t0 = acc[mt][pp][k], t1 = acc[mt][pp + 2][k];
                    acc[mt][pp][k]     = t0 * cs - t1 * sn;
                    acc[mt][pp + 2][k] = t1 * cs + t0 * sn;
                }
            }
        }
    }

#pragma unroll
    for (int mt = 0; mt < 4; mt++)
#pragma unroll
        for (int nt = 0; nt < 4; nt++) {
            int c = col0 + wn * 32 + nt * 8 + 2 * tq;
#pragma unroll
            for (int half = 0; half < 2; half++) {
                int m = row0 + wm * 64 + mt * 16 + g + half * 8;
                float2 val = make_float2(acc[mt][nt][half * 2], acc[mt][nt][half * 2 + 1]);
                if (MODE == 0) {
                    int bi = m >> 11, n = m & 2047, h = c >> 6, d = c & 63;
                    *(unsigned*)&Yh[(((size_t)(bi * HEADS + h) * SEQ + n) << 6) + d] =
                        f2h2(val.x, val.y);
                } else {
                    float2 bv = *(const float2*)&bo[c];
                    float2 rv = *(const float2*)&resid[(size_t)m * DIMD + c];
                    val.x += bv.x + rv.x;
                    val.y += bv.y + rv.y;
                    *(float2*)&Yf[(size_t)m * DIMD + c] = val;
                }
            }
        }
}

// ===== fused flash attention: 256 threads, 4(m)x2(n), ldmatrix frags =======
#define RB 144
__global__ __launch_bounds__(256) void fused_attn(float* __restrict__ S) {
    extern __shared__ char smraw[];
    uint32_t sb = smem_u32(smraw);
    uint32_t qb = sb, kb0 = sb + 18432, vb0 = sb + 55296;
    float* inv_s        = (float*)(smraw + 92160);
    float (*part)[2]    = (float (*)[2])(smraw + 92672);
    float (*obuf)[66]   = (float (*)[66])smraw;

    int t = threadIdx.x;
    int w = t >> 5, lane = t & 31, g = lane >> 2, tq = lane & 3;
    int wm = w & 3, wn = w >> 2;        // 4 m-groups x 2 n-groups
    int z = blockIdx.y;
    int i0 = blockIdx.x * 128;
    const __half* Qb = g_Q + (size_t)z * SEQ * DH;
    const __half* Kb = g_K + (size_t)z * SEQ * DH;
    const __half* Vb = g_V + (size_t)z * SEQ * DH;
    float* Sb = S + (size_t)z * SEQ * SEQ;

    int crow[4], cch[4];
#pragma unroll
    for (int s = 0; s < 4; s++) {
        int idx = t + s * 256;
        crow[s] = idx >> 3; cch[s] = (idx & 7) * 16;
    }

    // ---- issue Q + K(0), wait, hoist Q fragments into registers ----
#pragma unroll
    for (int s = 0; s < 4; s++) {
        CPA16(qb + crow[s] * RB + cch[s],
              (const char*)(Qb + (size_t)(i0 + crow[s]) * DH) + cch[s]);
        CPA16(kb0 + crow[s] * RB + cch[s],
              (const char*)(Kb + (size_t)crow[s] * DH) + cch[s]);
    }
    CPA_COMMIT();

    int mrb = wm * 32;
    int aro = (lane & 15);
    int akh = (lane >> 4) * 16;

    CPA_WAIT(0);
    __syncthreads();

    unsigned qf[4][2][4];   // [kc][mt][frag]
#pragma unroll
    for (int kc = 0; kc < 4; kc++)
#pragma unroll
        for (int mt = 0; mt < 2; mt++)
            ldsm_x4(qf[kc][mt][0], qf[kc][mt][1], qf[kc][mt][2], qf[kc][mt][3],
                    qb + (mrb + mt * 16 + aro) * RB + kc * 32 + akh);

    // prefetch K(1)
    {
        const __half* ksrc = Kb + (size_t)128 * DH;
#pragma unroll
        for (int s = 0; s < 4; s++)
            CPA16(kb0 + 18432 + crow[s] * RB + cch[s],
                  (const char*)(ksrc + (size_t)crow[s] * DH) + cch[s]);
        CPA_COMMIT();
    }

    // ======== PASS 1: row sums (Q frags hoisted) ========
    float rsum[2][2];
    rsum[0][0] = rsum[0][1] = rsum[1][0] = rsum[1][1] = 0.f;

    for (int p = 0; p < 16; p++) {
        uint32_t kcur = kb0 + (p & 1) * 18432;
        if (p + 2 < 16) {
            uint32_t kdst = kb0 + (p & 1) * 18432;  // placeholder (recomputed below)
            (void)kdst;
        }
        // K(p) ready when all-but-latest groups drained
        if (p + 1 < 16) { CPA_WAIT(1); } else { CPA_WAIT(0); }
        __syncthreads();

        // issue K(p+2) into buffer (p)&1 AFTER everyone synced past reading K(p-1)?
        // buffer reuse: K(p+2) uses buf p&1 == K(p)'s buf -> must issue only after
        // this iteration's reads of K(p) complete. So issue at END of body instead.

        float acc[2][8][4];
#pragma unroll
        for (int i = 0; i < 2; i++)
#pragma unroll
            for (int j = 0; j < 8; j++)
#pragma unroll
                for (int r = 0; r < 4; r++) acc[i][j][r] = 0.f;

#pragma unroll
        for (int kc = 0; kc < 4; kc++) {
            unsigned b[8][2];
#pragma unroll
            for (int nt2 = 0; nt2 < 4; nt2++) {
                unsigned r0, r1, r2, r3;
                ldsm_x4(r0, r1, r2, r3,
                        kcur + (wn * 64 + nt2 * 16 + aro) * RB + kc * 32 + akh);
                b[2 * nt2][0] = r0;     b[2 * nt2][1] = r2;
                b[2 * nt2 + 1][0] = r1; b[2 * nt2 + 1][1] = r3;
            }
#pragma unroll
            for (int mt = 0; mt < 2; mt++)
#pragma unroll
                for (int nt = 0; nt < 8; nt++)
                    mma_f16(acc[mt][nt], qf[kc][mt], b[nt], acc[mt][nt]);
        }
#pragma unroll
        for (int mt = 0; mt < 2; mt++)
#pragma unroll
            for (int nt = 0; nt < 8; nt++) {
                rsum[mt][0] += __expf(acc[mt][nt][0] * 0.125f) + __expf(acc[mt][nt][1] * 0.125f);
                rsum[mt][1] += __expf(acc[mt][nt][2] * 0.125f) + __expf(acc[mt][nt][3] * 0.125f);
            }
        __syncthreads();

        // now safe to overwrite buf p&1 with K(p+2)
        if (p + 2 < 16) {
            uint32_t kdst = kb0 + (p & 1) * 18432;
            const __half* ksrc = Kb + (size_t)(p + 2) * 128 * DH;
#pragma unroll
            for (int s = 0; s < 4; s++)
                CPA16(kdst + crow[s] * RB + cch[s],
                      (const char*)(ksrc + (size_t)crow[s] * DH) + cch[s]);
            CPA_COMMIT();
        }
    }

#pragma unroll
    for (int mt = 0; mt < 2; mt++)
#pragma unroll
        for (int half = 0; half < 2; half++) {
            float r = rsum[mt][half];
            r += __shfl_xor_sync(0xffffffffu, r, 1);
            r += __shfl_xor_sync(0xffffffffu, r, 2);
            if (tq == 0) part[mrb + mt * 16 + half * 8 + g][wn] = r;
        }
    __syncthreads();
    if (t < 128) inv_s[t] = 1.f / (part[t][0] + part[t][1]);

#pragma unroll
    for (int s = 0; s < 4; s++) {
        CPA16(kb0 + crow[s] * RB + cch[s],
              (const char*)(Kb + (size_t)crow[s] * DH) + cch[s]);
        CPA16(vb0 + crow[s] * RB + cch[s],
              (const char*)(Vb + (size_t)crow[s] * DH) + cch[s]);
    }
    CPA_COMMIT();

    // ======== PASS 2 ========
    float accO[2][8][4];
#pragma unroll
    for (int i = 0; i < 2; i++)
#pragma unroll
        for (int j = 0; j < 8; j++)
#pragma unroll
            for (int r = 0; r < 4; r++) accO[i][j][r] = 0.f;

    for (int p = 0; p < 16; p++) {
        uint32_t kcur = kb0 + (p & 1) * 18432;
        uint32_t vcur = vb0 + (p & 1) * 18432;
        if (p + 1 < 16) {
            uint32_t kdst = kb0 + ((p + 1) & 1) * 18432;
            uint32_t vdst = vb0 + ((p + 1) & 1) * 18432;
            const __half* ksrc = Kb + (size_t)(p + 1) * 128 * DH;
            const __half* vsrc = Vb + (size_t)(p + 1) * 128 * DH;
#pragma unroll
            for (int s = 0; s < 4; s++) {
                CPA16(kdst + crow[s] * RB + cch[s],
                      (const char*)(ksrc + (size_t)crow[s] * DH) + cch[s]);
                CPA16(vdst + crow[s] * RB + cch[s],
                      (const char*)(vsrc + (size_t)crow[s] * DH) + cch[s]);
            }
            CPA_COMMIT();
            CPA_WAIT(1);
        } else {
            CPA_WAIT(0);
        }
        __syncthreads();

        float acc[2][8][4];
#pragma unroll
        for (int i = 0; i < 2; i++)
#pragma unroll
            for (int j = 0; j < 8; j++)
#pragma unroll
                for (int r = 0; r < 4; r++) acc[i][j][r] = 0.f;

#pragma unroll
        for (int kc = 0; kc < 4; kc++) {
            unsigned a[2][4], b[8][2];
#pragma unroll
            for (int mt = 0; mt < 2; mt++)
                ldsm_x4(a[mt][0], a[mt][1], a[mt][2], a[mt][3],
                        qb + (mrb + mt * 16 + aro) * RB + kc * 32 + akh);
#pragma unroll
            for (int nt2 = 0; nt2 < 4; nt2++) {
                unsigned r0, r1, r2, r3;
                ldsm_x4(r0, r1, r2, r3,
                        kcur + (wn * 64 + nt2 * 16 + aro) * RB + kc * 32 + akh);
                b[2 * nt2][0] = r0;     b[2 * nt2][1] = r2;
                b[2 * nt2 + 1][0] = r1; b[2 * nt2 + 1][1] = r3;
            }
#pragma unroll
            for (int mt = 0; mt < 2; mt++)
#pragma unroll
                for (int nt = 0; nt < 8; nt++)
                    mma_f16(acc[mt][nt], a[mt], b[nt], acc[mt][nt]);
        }

        int j0 = p * 128;
#pragma unroll
        for (int mt = 0; mt < 2; mt++) {
            int mr0 = mrb + mt * 16 + g;
            float iv0 = inv_s[mr0];
            float iv1 = inv_s[mr0 + 8];
#pragma unroll
            for (int nt = 0; nt < 8; nt++) {
                acc[mt][nt][0] = __expf(acc[mt][nt][0] * 0.125f) * iv0;
                acc[mt][nt][1] = __expf(acc[mt][nt][1] * 0.125f) * iv0;
                acc[mt][nt][2] = __expf(acc[mt][nt][2] * 0.125f) * iv1;
                acc[mt][nt][3] = __expf(acc[mt][nt][3] * 0.125f) * iv1;
                int c = j0 + wn * 64 + nt * 8 + 2 * tq;
                stcs2(&Sb[(size_t)(i0 + mr0) * SEQ + c],     acc[mt][nt][0], acc[mt][nt][1]);
                stcs2(&Sb[(size_t)(i0 + mr0 + 8) * SEQ + c], acc[mt][nt][2], acc[mt][nt][3]);
            }
        }

        // PV over warp's 64-col k-slice (4 chunks of k16)
#pragma unroll
        for (int s = 0; s < 4; s++) {
            unsigned bV[8][2];
#pragma unroll
            for (int nt2 = 0; nt2 < 4; nt2++) {
                unsigned r0, r1, r2, r3;
                ldsm_x4_t(r0, r1, r2, r3,
                          vcur + (wn * 64 + s * 16 + aro) * RB
                               + (nt2 * 16 + (lane >> 4) * 8) * 2);
                bV[2 * nt2][0] = r0;     bV[2 * nt2][1] = r1;
                bV[2 * nt2 + 1][0] = r2; bV[2 * nt2 + 1][1] = r3;
            }
#pragma unroll
            for (int mt = 0; mt < 2; mt++) {
                unsigned aP[4];
                aP[0] = f2h2(acc[mt][2*s][0],   acc[mt][2*s][1]);
                aP[1] = f2h2(acc[mt][2*s][2],   acc[mt][2*s][3]);
                aP[2] = f2h2(acc[mt][2*s+1][0], acc[mt][2*s+1][1]);
                aP[3] = f2h2(acc[mt][2*s+1][2], acc[mt][2*s+1][3]);
#pragma unroll
                for (int nt = 0; nt < 8; nt++)
                    mma_f16(accO[mt][nt], aP, bV[nt], accO[mt][nt]);
            }
        }
        __syncthreads();
    }

    // ---- cross-warp O reduce (over wn: 2 partners) ----
    __syncthreads();
#pragma unroll
    for (int p = 0; p < 2; p++) {
        if (wn == p) {
#pragma unroll
            for (int mt = 0; mt < 2; mt++) {
                int r0 = mrb + mt * 16 + g;
#pragma unroll
                for (int nt = 0; nt < 8; nt++) {
                    int c = nt * 8 + 2 * tq;
                    if (p == 0) {
                        *(float2*)&obuf[r0][c]     = make_float2(accO[mt][nt][0], accO[mt][nt][1]);
                        *(float2*)&obuf[r0 + 8][c] = make_float2(accO[mt][nt][2], accO[mt][nt][3]);
                    } else {
                        float2 o0 = *(float2*)&obuf[r0][c];
                        float2 o1 = *(float2*)&obuf[r0 + 8][c];
                        o0.x += accO[mt][nt][0]; o0.y += accO[mt][nt][1];
                        o1.x += accO[mt][nt][2]; o1.y += accO[mt][nt][3];
                        *(float2*)&obuf[r0][c] = o0;
                        *(float2*)&obuf[r0 + 8][c] = o1;
                    }
                }
            }
        }
        __syncthreads();
    }

    // write O (half): [b, n, h*64+d]
    int bi = z >> 4, h = z & 15;
#pragma unroll
    for (int it = 0; it < 8; it++) {
        int idx = t + it * 256;
        int m = idx >> 4, c4 = (idx & 15) * 4;
        uint2 v = make_uint2(f2h2(obuf[m][c4], obuf[m][c4 + 1]),
                             f2h2(obuf[m][c4 + 2], obuf[m][c4 + 3]));
        *(uint2*)&g_O[((size_t)bi * SEQ + i0 + m) * DIMD + h * 64 + c4] = v;
    }
}

// ---------------------------- launcher -------------------------------------
extern "C" void kernel_launch(void* const* d_in, const int* in_sizes, int n_in,
                              void* d_out, int out_size) {
    const float* x    = (const float*)d_in[0];
    const float* rope = (const float*)d_in[1];
    const float* Wq   = (const float*)d_in[2];
    const float* Wk   = (const float*)d_in[3];
    const float* Wv   = (const float*)d_in[4];
    const float* Wo   = (const float*)d_in[5];
    const float* bo   = (const float*)d_in[6];

    float* out  = (float*)d_out;
    float* attn = out + OUT_ELEMS;

    __half *Xp, *Whp, *Op;
    cudaGetSymbolAddress((void**)&Xp,  g_X);
    cudaGetSymbolAddress((void**)&Whp, g_Wh);
    cudaGetSymbolAddress((void**)&Op,  g_O);

    const int FA_SMEM = 93696;
    const int GP_SMEM = 37888;
    cudaFuncSetAttribute(fused_attn, cudaFuncAttributeMaxDynamicSharedMemorySize, FA_SMEM);

    convert_half<<<(int)((OUT_ELEMS / 4 + 4 * DIMD * DIMD / 4) / 256), 256>>>(x, Wq, Wk, Wv, Wo);

    gemm_pipe<0><<<dim3(8, 64, 3), 256, GP_SMEM>>>(Xp, Whp, nullptr, nullptr, rope, nullptr);

    fused_attn<<<dim3(16, 64), 256, FA_SMEM>>>(attn);

    gemm_pipe<1><<<dim3(8, 64), 256, GP_SMEM>>>(Op, Whp + 3 * (size_t)DIMD * DIMD, bo, x, nullptr, out);
}

// round 17
// speedup vs baseline: 1.1777x; 1.0351x over previous
#include <cuda_runtime.h>
#include <cuda_fp16.h>
#include <math.h>
#include <stdint.h>

#define BB     4
#define SEQ    2048
#define DIMD   1024
#define HEADS  16
#define DH     64
#define ROT    32
#define BH     (BB*HEADS)          // 64
#define MROWS  (BB*SEQ)            // 8192
#define OUT_ELEMS ((size_t)MROWS*DIMD)

// ---------------- scratch (fp16) ----------------
__device__ __half g_Q[(size_t)BH*SEQ*DH];
__device__ __half g_K[(size_t)BH*SEQ*DH];
__device__ __half g_V[(size_t)BH*SEQ*DH];
__device__ __half g_O[(size_t)MROWS*DIMD];
__device__ __half g_X[(size_t)MROWS*DIMD];
__device__ __half g_Wh[(size_t)4*DIMD*DIMD];

// ---------------- helpers ----------------
__device__ __forceinline__ unsigned f2h2(float a, float b) {
    unsigned u;
    asm("cvt.rn.f16x2.f32 %0, %2, %1;" : "=r"(u) : "f"(a), "f"(b));
    return u;
}
__device__ __forceinline__ uint32_t smem_u32(const void* p) {
    uint32_t a;
    asm("{ .reg .u64 t; cvta.to.shared.u64 t, %1; cvt.u32.u64 %0, t; }" : "=r"(a) : "l"(p));
    return a;
}
__device__ __forceinline__ void mma_f16(float d[4], const unsigned a[4],
                                        const unsigned b[2], const float c[4]) {
    asm volatile(
        "mma.sync.aligned.m16n8k16.row.col.f32.f16.f16.f32 "
        "{%0,%1,%2,%3}, {%4,%5,%6,%7}, {%8,%9}, {%10,%11,%12,%13};"
        : "=f"(d[0]), "=f"(d[1]), "=f"(d[2]), "=f"(d[3])
        : "r"(a[0]), "r"(a[1]), "r"(a[2]), "r"(a[3]),
          "r"(b[0]), "r"(b[1]),
          "f"(c[0]), "f"(c[1]), "f"(c[2]), "f"(c[3]));
}
__device__ __forceinline__ void ldsm_x4(unsigned& r0, unsigned& r1,
                                        unsigned& r2, unsigned& r3, uint32_t a) {
    asm volatile("ldmatrix.sync.aligned.m8n8.x4.shared.b16 {%0,%1,%2,%3}, [%4];"
                 : "=r"(r0), "=r"(r1), "=r"(r2), "=r"(r3) : "r"(a));
}
__device__ __forceinline__ void ldsm_x4_t(unsigned& r0, unsigned& r1,
                                          unsigned& r2, unsigned& r3, uint32_t a) {
    asm volatile("ldmatrix.sync.aligned.m8n8.x4.trans.shared.b16 {%0,%1,%2,%3}, [%4];"
                 : "=r"(r0), "=r"(r1), "=r"(r2), "=r"(r3) : "r"(a));
}
#define CPA16(d, s)   asm volatile("cp.async.ca.shared.global [%0], [%1], 16;" :: "r"(d), "l"(s))
#define CPA_COMMIT()  asm volatile("cp.async.commit_group;" ::: "memory")
#define CPA_WAIT(n)   asm volatile("cp.async.wait_group %0;" :: "n"(n) : "memory")
__device__ __forceinline__ void stcs2(float* p, float x, float y) {
    asm volatile("st.global.cs.v2.f32 [%0], {%1,%2};" :: "l"(p), "f"(x), "f"(y));
}

// ---------------- f32 -> f16 conversion (x + 4 weights) ----------------
__global__ void convert_half(const float* __restrict__ x,
                             const float* __restrict__ Wq, const float* __restrict__ Wk,
                             const float* __restrict__ Wv, const float* __restrict__ Wo) {
    size_t i = (size_t)blockIdx.x * blockDim.x + threadIdx.x;
    const size_t XN = OUT_ELEMS / 4;
    const size_t WN = (size_t)DIMD * DIMD / 4;
    const float* src; __half* dst; size_t off;
    if (i < XN)                { src = x;  dst = g_X;               off = i; }
    else if (i < XN + WN)      { src = Wq; dst = g_Wh;              off = i - XN; }
    else if (i < XN + 2 * WN)  { src = Wk; dst = g_Wh + WN * 4;     off = i - XN - WN; }
    else if (i < XN + 3 * WN)  { src = Wv; dst = g_Wh + 2 * WN * 4; off = i - XN - 2 * WN; }
    else                       { src = Wo; dst = g_Wh + 3 * WN * 4; off = i - XN - 3 * WN; }
    float4 v = *(const float4*)(src + off * 4);
    *(uint2*)(dst + off * 4) = make_uint2(f2h2(v.x, v.y), f2h2(v.z, v.w));
}

// ===== pipelined fp16 GEMM: 3-stage cp.async, 1 sync/iter, 2 CTA/SM ========
// MODE 0: proj q/k/v, head-major half out, rope fused in epilogue.
// MODE 1: final (f32 out + bias + resid)
#define A_STRIDE 80
#define B_STRIDE 272
#define GBUF 18944    // A 10240 + B 8704
template <int MODE>
__global__ __launch_bounds__(256, 2) void gemm_pipe(
    const __half* __restrict__ Aglob, const __half* __restrict__ Wbase,
    const float* __restrict__ bo, const float* __restrict__ resid,
    const float* __restrict__ ropet, float* __restrict__ Yf)
{
    extern __shared__ char sm[];
    uint32_t sb = smem_u32(sm);

    int t = threadIdx.x, lane = t & 31, w = t >> 5;
    int g = lane >> 2, tq = lane & 3;
    int wm = w & 1, wn = w >> 1;
    int row0 = blockIdx.y * 128, col0 = blockIdx.x * 128;

    const __half* Bh;
    __half* Yh = nullptr;
    if (MODE == 0) {
        int z = blockIdx.z;
        Bh = Wbase + (size_t)z * DIMD * DIMD;
        Yh = (z == 0) ? g_Q : (z == 1) ? g_K : g_V;
    } else {
        Bh = Wbase;
    }

    float acc[4][4][4];
#pragma unroll
    for (int i = 0; i < 4; i++)
#pragma unroll
        for (int j = 0; j < 4; j++)
#pragma unroll
            for (int r = 0; r < 4; r++) acc[i][j][r] = 0.f;

    int ar[2], ac[2], br[2], bc[2];
#pragma unroll
    for (int s = 0; s < 2; s++) {
        int idx = t + s * 256;
        ar[s] = idx >> 2;  ac[s] = (idx & 3) * 16;
        br[s] = idx >> 4;  bc[s] = (idx & 15) * 16;
    }

#define ISSUE(p, buf) do { \
    int _k0 = (p) * 32; \
    uint32_t _ab = sb + (buf) * GBUF, _bb = _ab + 10240; \
    _Pragma("unroll") \
    for (int s = 0; s < 2; s++) { \
        CPA16(_ab + ar[s] * A_STRIDE + ac[s], \
              (const char*)(Aglob + (size_t)(row0 + ar[s]) * DIMD + _k0) + ac[s]); \
        CPA16(_bb + br[s] * B_STRIDE + bc[s], \
              (const char*)(Bh + (size_t)(_k0 + br[s]) * DIMD + col0) + bc[s]); \
    } \
    CPA_COMMIT(); \
} while (0)

    ISSUE(0, 0);
    ISSUE(1, 1);

    int buf = 0;
    for (int p = 0; p < 32; p++) {
        if (p + 1 < 32) { CPA_WAIT(1); } else { CPA_WAIT(0); }
        __syncthreads();
        if (p + 2 < 32) {
            int nb = buf + 2; if (nb >= 3) nb -= 3;
            ISSUE(p + 2, nb);
        }
        uint32_t ab = sb + buf * GBUF, bb = ab + 10240;
#pragma unroll
        for (int ks = 0; ks < 2; ks++) {
            int kh = ks * 16;
            unsigned a[4][4], b[4][2];
#pragma unroll
            for (int mt = 0; mt < 4; mt++) {
                uint32_t addr = ab + (wm * 64 + mt * 16 + (lane & 15)) * A_STRIDE
                              + (kh + (lane >> 4) * 8) * 2;
                ldsm_x4(a[mt][0], a[mt][1], a[mt][2], a[mt][3], addr);
            }
#pragma unroll
            for (int nt2 = 0; nt2 < 2; nt2++) {
                unsigned r0, r1, r2, r3;
                uint32_t addr = bb + (kh + (lane & 15)) * B_STRIDE
                              + (wn * 32 + nt2 * 16 + (lane >> 4) * 8) * 2;
                ldsm_x4_t(r0, r1, r2, r3, addr);
                b[nt2 * 2][0] = r0;     b[nt2 * 2][1] = r1;
                b[nt2 * 2 + 1][0] = r2; b[nt2 * 2 + 1][1] = r3;
            }
#pragma unroll
            for (int mt = 0; mt < 4; mt++)
#pragma unroll
                for (int nt = 0; nt < 4; nt++)
                    mma_f16(acc[mt][nt], a[mt], b[nt], acc[mt][nt]);
        }
        buf++; if (buf == 3) buf = 0;
    }
#undef ISSUE

    // ---- fused partial RoPE (MODE 0, warps covering head-dims [0,32)) ----
    if (MODE == 0 && (wn & 1) == 0) {
#pragma unroll
        for (int mt = 0; mt < 4; mt++) {
#pragma unroll
            for (int pp = 0; pp < 2; pp++) {
#pragma unroll
                for (int k = 0; k < 4; k++) {
                    int m = row0 + wm * 64 + mt * 16 + g + (k >> 1) * 8;
                    int n = m & (SEQ - 1);
                    int d = pp * 8 + 2 * tq + (k & 1);
                    float ang = ropet[n * ROT + d];
                    float cs, sn;
                    __sincosf(ang, &sn, &cs);
                    float t0 = acc[mt][pp][k], t1 = acc[mt][pp + 2][k];
                    acc[mt][pp][k]     = t0 * cs - t1 * sn;
                    acc[mt][pp + 2][k] = t1 * cs + t0 * sn;
                }
            }
        }
    }

#pragma unroll
    for (int mt = 0; mt < 4; mt++)
#pragma unroll
        for (int nt = 0; nt < 4; nt++) {
            int c = col0 + wn * 32 + nt * 8 + 2 * tq;
#pragma unroll
            for (int half = 0; half < 2; half++) {
                int m = row0 + wm * 64 + mt * 16 + g + half * 8;
                float2 val = make_float2(acc[mt][nt][half * 2], acc[mt][nt][half * 2 + 1]);
                if (MODE == 0) {
                    int bi = m >> 11, n = m & 2047, h = c >> 6, d = c & 63;
                    *(unsigned*)&Yh[(((size_t)(bi * HEADS + h) * SEQ + n) << 6) + d] =
                        f2h2(val.x, val.y);
                } else {
                    float2 bv = *(const float2*)&bo[c];
                    float2 rv = *(const float2*)&resid[(size_t)m * DIMD + c];
                    val.x += bv.x + rv.x;
                    val.y += bv.y + rv.y;
                    *(float2*)&Yf[(size_t)m * DIMD + c] = val;
                }
            }
        }
}

// ===== fused flash attention: 3-stage pipes, 1 sync/iter ====================
#define RB 144
#define KVB 18432
__global__ __launch_bounds__(256) void fused_attn(float* __restrict__ S) {
    extern __shared__ char smraw[];
    uint32_t sb = smem_u32(smraw);
    uint32_t qb = sb;
    uint32_t kb = sb + KVB;              // 3 bufs
    uint32_t vb = sb + 4 * KVB;          // 3 bufs
    float* inv_s        = (float*)(smraw + 7 * KVB);
    float (*part)[2]    = (float (*)[2])(smraw + 7 * KVB + 512);
    float (*obuf)[66]   = (float (*)[66])smraw;

    int t = threadIdx.x;
    int w = t >> 5, lane = t & 31, g = lane >> 2, tq = lane & 3;
    int wm = w & 3, wn = w >> 2;        // 4 m-groups x 2 n-groups
    int z = blockIdx.y;
    int i0 = blockIdx.x * 128;
    const __half* Qb = g_Q + (size_t)z * SEQ * DH;
    const __half* Kb = g_K + (size_t)z * SEQ * DH;
    const __half* Vb = g_V + (size_t)z * SEQ * DH;
    float* Sb = S + (size_t)z * SEQ * SEQ;

    int crow[4], cch[4];
#pragma unroll
    for (int s = 0; s < 4; s++) {
        int idx = t + s * 256;
        crow[s] = idx >> 3; cch[s] = (idx & 7) * 16;
    }

#define ISSUE_K(p, buf) do { \
    const __half* _src = Kb + (size_t)(p) * 128 * DH; \
    uint32_t _d = kb + (buf) * KVB; \
    _Pragma("unroll") \
    for (int s = 0; s < 4; s++) \
        CPA16(_d + crow[s] * RB + cch[s], (const char*)(_src + (size_t)crow[s] * DH) + cch[s]); \
    CPA_COMMIT(); \
} while (0)

#define ISSUE_KV(p, buf) do { \
    const __half* _ks = Kb + (size_t)(p) * 128 * DH; \
    const __half* _vs = Vb + (size_t)(p) * 128 * DH; \
    uint32_t _kd = kb + (buf) * KVB, _vd = vb + (buf) * KVB; \
    _Pragma("unroll") \
    for (int s = 0; s < 4; s++) { \
        CPA16(_kd + crow[s] * RB + cch[s], (const char*)(_ks + (size_t)crow[s] * DH) + cch[s]); \
        CPA16(_vd + crow[s] * RB + cch[s], (const char*)(_vs + (size_t)crow[s] * DH) + cch[s]); \
    } \
    CPA_COMMIT(); \
} while (0)

    // ---- prologue: Q + K(0); hoist Q fragments ----
#pragma unroll
    for (int s = 0; s < 4; s++)
        CPA16(qb + crow[s] * RB + cch[s],
              (const char*)(Qb + (size_t)(i0 + crow[s]) * DH) + cch[s]);
    ISSUE_K(0, 0);

    int mrb = wm * 32;
    int aro = (lane & 15);
    int akh = (lane >> 4) * 16;

    CPA_WAIT(0);
    __syncthreads();

    unsigned qf[4][2][4];
#pragma unroll
    for (int kc = 0; kc < 4; kc++)
#pragma unroll
        for (int mt = 0; mt < 2; mt++)
            ldsm_x4(qf[kc][mt][0], qf[kc][mt][1], qf[kc][mt][2], qf[kc][mt][3],
                    qb + (mrb + mt * 16 + aro) * RB + kc * 32 + akh);

    ISSUE_K(1, 1);

    // ======== PASS 1: row sums (1 sync/iter, 3 bufs) ========
    float rsum[2][2];
    rsum[0][0] = rsum[0][1] = rsum[1][0] = rsum[1][1] = 0.f;

    int buf = 0;
    for (int p = 0; p < 16; p++) {
        if (p > 0) {
            if (p + 1 < 16) { CPA_WAIT(1); } else { CPA_WAIT(0); }
            __syncthreads();
        }
        if (p + 2 < 16) {
            int nb = buf + 2; if (nb >= 3) nb -= 3;
            ISSUE_K(p + 2, nb);
        }
        uint32_t kcur = kb + buf * KVB;

        float acc[2][8][4];
#pragma unroll
        for (int i = 0; i < 2; i++)
#pragma unroll
            for (int j = 0; j < 8; j++)
#pragma unroll
                for (int r = 0; r < 4; r++) acc[i][j][r] = 0.f;

#pragma unroll
        for (int kc = 0; kc < 4; kc++) {
            unsigned b[8][2];
#pragma unroll
            for (int nt2 = 0; nt2 < 4; nt2++) {
                unsigned r0, r1, r2, r3;
                ldsm_x4(r0, r1, r2, r3,
                        kcur + (wn * 64 + nt2 * 16 + aro) * RB + kc * 32 + akh);
                b[2 * nt2][0] = r0;     b[2 * nt2][1] = r2;
                b[2 * nt2 + 1][0] = r1; b[2 * nt2 + 1][1] = r3;
            }
#pragma unroll
            for (int mt = 0; mt < 2; mt++)
#pragma unroll
                for (int nt = 0; nt < 8; nt++)
                    mma_f16(acc[mt][nt], qf[kc][mt], b[nt], acc[mt][nt]);
        }
#pragma unroll
        for (int mt = 0; mt < 2; mt++)
#pragma unroll
            for (int nt = 0; nt < 8; nt++) {
                rsum[mt][0] += __expf(acc[mt][nt][0] * 0.125f) + __expf(acc[mt][nt][1] * 0.125f);
                rsum[mt][1] += __expf(acc[mt][nt][2] * 0.125f) + __expf(acc[mt][nt][3] * 0.125f);
            }
        buf++; if (buf == 3) buf = 0;
    }

#pragma unroll
    for (int mt = 0; mt < 2; mt++)
#pragma unroll
        for (int half = 0; half < 2; half++) {
            float r = rsum[mt][half];
            r += __shfl_xor_sync(0xffffffffu, r, 1);
            r += __shfl_xor_sync(0xffffffffu, r, 2);
            if (tq == 0) part[mrb + mt * 16 + half * 8 + g][wn] = r;
        }
    __syncthreads();
    if (t < 128) inv_s[t] = 1.f / (part[t][0] + part[t][1]);

    // pass-2 prologue (after the sync above -> all pass-1 reads done)
    ISSUE_KV(0, 0);
    ISSUE_KV(1, 1);

    // ======== PASS 2 ========
    float accO[2][8][4];
#pragma unroll
    for (int i = 0; i < 2; i++)
#pragma unroll
        for (int j = 0; j < 8; j++)
#pragma unroll
            for (int r = 0; r < 4; r++) accO[i][j][r] = 0.f;

    buf = 0;
    for (int p = 0; p < 16; p++) {
        if (p + 1 < 16) { CPA_WAIT(1); } else { CPA_WAIT(0); }
        __syncthreads();
        if (p + 2 < 16) {
            int nb = buf + 2; if (nb >= 3) nb -= 3;
            ISSUE_KV(p + 2, nb);
        }
        uint32_t kcur = kb + buf * KVB;
        uint32_t vcur = vb + buf * KVB;

        float acc[2][8][4];
#pragma unroll
        for (int i = 0; i < 2; i++)
#pragma unroll
            for (int j = 0; j < 8; j++)
#pragma unroll
                for (int r = 0; r < 4; r++) acc[i][j][r] = 0.f;

#pragma unroll
        for (int kc = 0; kc < 4; kc++) {
            unsigned b[8][2];
#pragma unroll
            for (int nt2 = 0; nt2 < 4; nt2++) {
                unsigned r0, r1, r2, r3;
                ldsm_x4(r0, r1, r2, r3,
                        kcur + (wn * 64 + nt2 * 16 + aro) * RB + kc * 32 + akh);
                b[2 * nt2][0] = r0;     b[2 * nt2][1] = r2;
                b[2 * nt2 + 1][0] = r1; b[2 * nt2 + 1][1] = r3;
            }
#pragma unroll
            for (int mt = 0; mt < 2; mt++)
#pragma unroll
                for (int nt = 0; nt < 8; nt++)
                    mma_f16(acc[mt][nt], qf[kc][mt], b[nt], acc[mt][nt]);
        }

        int j0 = p * 128;
#pragma unroll
        for (int mt = 0; mt < 2; mt++) {
            int mr0 = mrb + mt * 16 + g;
            float iv0 = inv_s[mr0];
            float iv1 = inv_s[mr0 + 8];
#pragma unroll
            for (int nt = 0; nt < 8; nt++) {
                acc[mt][nt][0] = __expf(acc[mt][nt][0] * 0.125f) * iv0;
                acc[mt][nt][1] = __expf(acc[mt][nt][1] * 0.125f) * iv0;
                acc[mt][nt][2] = __expf(acc[mt][nt][2] * 0.125f) * iv1;
                acc[mt][nt][3] = __expf(acc[mt][nt][3] * 0.125f) * iv1;
                int c = j0 + wn * 64 + nt * 8 + 2 * tq;
                stcs2(&Sb[(size_t)(i0 + mr0) * SEQ + c],     acc[mt][nt][0], acc[mt][nt][1]);
                stcs2(&Sb[(size_t)(i0 + mr0 + 8) * SEQ + c], acc[mt][nt][2], acc[mt][nt][3]);
            }
        }

        // PV over warp's 64-col k-slice (4 chunks of k16)
#pragma unroll
        for (int s = 0; s < 4; s++) {
            unsigned bV[8][2];
#pragma unroll
            for (int nt2 = 0; nt2 < 4; nt2++) {
                unsigned r0, r1, r2, r3;
                ldsm_x4_t(r0, r1, r2, r3,
                          vcur + (wn * 64 + s * 16 + aro) * RB
                               + (nt2 * 16 + (lane >> 4) * 8) * 2);
                bV[2 * nt2][0] = r0;     bV[2 * nt2][1] = r1;
                bV[2 * nt2 + 1][0] = r2; bV[2 * nt2 + 1][1] = r3;
            }
#pragma unroll
            for (int mt = 0; mt < 2; mt++) {
                unsigned aP[4];
                aP[0] = f2h2(acc[mt][2*s][0],   acc[mt][2*s][1]);
                aP[1] = f2h2(acc[mt][2*s][2],   acc[mt][2*s][3]);
                aP[2] = f2h2(acc[mt][2*s+1][0], acc[mt][2*s+1][1]);
                aP[3] = f2h2(acc[mt][2*s+1][2], acc[mt][2*s+1][3]);
#pragma unroll
                for (int nt = 0; nt < 8; nt++)
                    mma_f16(accO[mt][nt], aP, bV[nt], accO[mt][nt]);
            }
        }
        buf++; if (buf == 3) buf = 0;
    }

    // ---- cross-warp O reduce (over wn: 2 partners) ----
    __syncthreads();
#pragma unroll
    for (int p = 0; p < 2; p++) {
        if (wn == p) {
#pragma unroll
            for (int mt = 0; mt < 2; mt++) {
                int r0 = mrb + mt * 16 + g;
#pragma unroll
                for (int nt = 0; nt < 8; nt++) {
                    int c = nt * 8 + 2 * tq;
                    if (p == 0) {
                        *(float2*)&obuf[r0][c]     = make_float2(accO[mt][nt][0], accO[mt][nt][1]);
                        *(float2*)&obuf[r0 + 8][c] = make_float2(accO[mt][nt][2], accO[mt][nt][3]);
                    } else {
                        float2 o0 = *(float2*)&obuf[r0][c];
                        float2 o1 = *(float2*)&obuf[r0 + 8][c];
                        o0.x += accO[mt][nt][0]; o0.y += accO[mt][nt][1];
                        o1.x += accO[mt][nt][2]; o1.y += accO[mt][nt][3];
                        *(float2*)&obuf[r0][c] = o0;
                        *(float2*)&obuf[r0 + 8][c] = o1;
                    }
                }
            }
        }
        __syncthreads();
    }

    // write O (half): [b, n, h*64+d]
    int bi = z >> 4, h = z & 15;
#pragma unroll
    for (int it = 0; it < 8; it++) {
        int idx = t + it * 256;
        int m = idx >> 4, c4 = (idx & 15) * 4;
        uint2 v = make_uint2(f2h2(obuf[m][c4], obuf[m][c4 + 1]),
                             f2h2(obuf[m][c4 + 2], obuf[m][c4 + 3]));
        *(uint2*)&g_O[((size_t)bi * SEQ + i0 + m) * DIMD + h * 64 + c4] = v;
    }
#undef ISSUE_K
#undef ISSUE_KV
}

// ---------------------------- launcher -------------------------------------
extern "C" void kernel_launch(void* const* d_in, const int* in_sizes, int n_in,
                              void* d_out, int out_size) {
    const float* x    = (const float*)d_in[0];
    const float* rope = (const float*)d_in[1];
    const float* Wq   = (const float*)d_in[2];
    const float* Wk   = (const float*)d_in[3];
    const float* Wv   = (const float*)d_in[4];
    const float* Wo   = (const float*)d_in[5];
    const float* bo   = (const float*)d_in[6];

    float* out  = (float*)d_out;
    float* attn = out + OUT_ELEMS;

    __half *Xp, *Whp, *Op;
    cudaGetSymbolAddress((void**)&Xp,  g_X);
    cudaGetSymbolAddress((void**)&Whp, g_Wh);
    cudaGetSymbolAddress((void**)&Op,  g_O);

    const int FA_SMEM = 7 * 18432 + 512 + 1024;   // 130560
    const int GP_SMEM = 3 * 18944;                // 56832
    cudaFuncSetAttribute(fused_attn, cudaFuncAttributeMaxDynamicSharedMemorySize, FA_SMEM);
    cudaFuncSetAttribute(gemm_pipe<0>, cudaFuncAttributeMaxDynamicSharedMemorySize, GP_SMEM);
    cudaFuncSetAttribute(gemm_pipe<1>, cudaFuncAttributeMaxDynamicSharedMemorySize, GP_SMEM);

    convert_half<<<(int)((OUT_ELEMS / 4 + 4 * DIMD * DIMD / 4) / 256), 256>>>(x, Wq, Wk, Wv, Wo);

    gemm_pipe<0><<<dim3(8, 64, 3), 256, GP_SMEM>>>(Xp, Whp, nullptr, nullptr, rope, nullptr);

    fused_attn<<<dim3(16, 64), 256, FA_SMEM>>>(attn);

    gemm_pipe<1><<<dim3(8, 64), 256, GP_SMEM>>>(Op, Whp + 3 * (size_t)DIMD * DIMD, bo, x, nullptr, out);
}